// round 1
// baseline (speedup 1.0000x reference)
#include <cuda_runtime.h>
#include <math.h>

#define N_NODES 65536
#define N_EDGES 1048576
#define IN_FEATS 128
#define H1 128
#define H2 256
#define N_CLASSES 16

// Scratch (allocation-free rule: __device__ globals)
__device__ float g_y[(size_t)N_NODES * H1];       // relu(x@Wp^T + bp)
__device__ float g_pooled[(size_t)N_NODES * H1];  // segment max
__device__ float g_h[(size_t)N_NODES * H1];       // after conv combine
__device__ float g_h2[(size_t)N_NODES * H2];      // after W1

// ---------------------------------------------------------------------------
// Activations: 0 = none, 1 = relu, 2 = leaky_relu(0.01)
template <int ACT>
__device__ __forceinline__ float act_fn(float v) {
    if (ACT == 1) return v > 0.f ? v : 0.f;
    if (ACT == 2) return v > 0.f ? v : 0.01f * v;
    return v;
}

// ---------------------------------------------------------------------------
// Zero-init pooled (must happen every replay; atomicMax needs clean base)
__global__ void zero_pooled_kernel(float* pooled) {
    int i = blockIdx.x * blockDim.x + threadIdx.x;
    if (i < N_NODES * H1 / 4) {
        ((float4*)pooled)[i] = make_float4(0.f, 0.f, 0.f, 0.f);
    }
}

// ---------------------------------------------------------------------------
// SGEMM: C[M,N] = act( A[M,K] @ B[N,K]^T  (+ A2@B2^T)  + bias[N] )
// BM=BN=128, BK=16, 256 threads, 8x8 per-thread microtile.
template <int ACT, bool HAS2>
__global__ void __launch_bounds__(256) sgemm_kernel(
    const float* __restrict__ A, const float* __restrict__ B,
    const float* __restrict__ A2, const float* __restrict__ B2,
    const float* __restrict__ bias, float* __restrict__ C,
    int M, int N, int K)
{
    const int BK = 16;
    __shared__ float As[BK][128];
    __shared__ float Bs[BK][128];

    const int m0 = blockIdx.x * 128;
    const int n0 = blockIdx.y * 128;
    const int tid = threadIdx.x;
    const int tx = tid & 15;   // 16 cols of threads
    const int ty = tid >> 4;   // 16 rows of threads

    float acc[8][8];
#pragma unroll
    for (int i = 0; i < 8; i++)
#pragma unroll
        for (int j = 0; j < 8; j++) acc[i][j] = 0.f;

    const int passes = HAS2 ? 2 : 1;
    for (int p = 0; p < passes; p++) {
        const float* Ap = (HAS2 && p == 1) ? A2 : A;
        const float* Bp = (HAS2 && p == 1) ? B2 : B;

        for (int k0 = 0; k0 < K; k0 += BK) {
            // Load 128x16 A tile and 128x16 B tile (B is [N,K] row-major).
            // 512 float4 each; 256 threads -> 2 per thread per tile.
#pragma unroll
            for (int it = 0; it < 2; it++) {
                int idx = tid + it * 256;     // 0..511
                int row = idx >> 2;           // 0..127
                int kc = idx & 3;             // float4 index in K
                float4 a = *(const float4*)&Ap[(size_t)(m0 + row) * K + k0 + kc * 4];
                As[kc * 4 + 0][row] = a.x;
                As[kc * 4 + 1][row] = a.y;
                As[kc * 4 + 2][row] = a.z;
                As[kc * 4 + 3][row] = a.w;
                float4 b = *(const float4*)&Bp[(size_t)(n0 + row) * K + k0 + kc * 4];
                Bs[kc * 4 + 0][row] = b.x;
                Bs[kc * 4 + 1][row] = b.y;
                Bs[kc * 4 + 2][row] = b.z;
                Bs[kc * 4 + 3][row] = b.w;
            }
            __syncthreads();

#pragma unroll
            for (int k = 0; k < BK; k++) {
                float aF[8], bF[8];
                float4 a0 = *(const float4*)&As[k][ty * 8];
                float4 a1 = *(const float4*)&As[k][ty * 8 + 4];
                aF[0] = a0.x; aF[1] = a0.y; aF[2] = a0.z; aF[3] = a0.w;
                aF[4] = a1.x; aF[5] = a1.y; aF[6] = a1.z; aF[7] = a1.w;
                float4 b0 = *(const float4*)&Bs[k][tx * 8];
                float4 b1 = *(const float4*)&Bs[k][tx * 8 + 4];
                bF[0] = b0.x; bF[1] = b0.y; bF[2] = b0.z; bF[3] = b0.w;
                bF[4] = b1.x; bF[5] = b1.y; bF[6] = b1.z; bF[7] = b1.w;
#pragma unroll
                for (int i = 0; i < 8; i++)
#pragma unroll
                    for (int j = 0; j < 8; j++)
                        acc[i][j] += aF[i] * bF[j];
            }
            __syncthreads();
        }
    }

    // Epilogue
#pragma unroll
    for (int i = 0; i < 8; i++) {
        int row = m0 + ty * 8 + i;
#pragma unroll
        for (int j = 0; j < 8; j += 4) {
            int col = n0 + tx * 8 + j;
            float4 v;
            v.x = act_fn<ACT>(acc[i][j + 0] + bias[col + 0]);
            v.y = act_fn<ACT>(acc[i][j + 1] + bias[col + 1]);
            v.z = act_fn<ACT>(acc[i][j + 2] + bias[col + 2]);
            v.w = act_fn<ACT>(acc[i][j + 3] + bias[col + 3]);
            *(float4*)&C[(size_t)row * N + col] = v;
        }
    }
}

// ---------------------------------------------------------------------------
// Edge scatter-max: pooled[dst] = max(pooled[dst], y[src]) elementwise.
// y >= 0 (post-relu), so integer atomicMax on float bits is exact.
// One warp per edge; lane handles 4 contiguous floats (float4 gather).
__global__ void __launch_bounds__(256) scatter_max_kernel(
    const int* __restrict__ src, const int* __restrict__ dst,
    const float* __restrict__ y, float* __restrict__ pooled)
{
    int gid = blockIdx.x * blockDim.x + threadIdx.x;
    int e = gid >> 5;
    if (e >= N_EDGES) return;
    int lane = gid & 31;
    int s = __ldg(&src[e]);
    int d = __ldg(&dst[e]);
    float4 v = *(const float4*)&y[(size_t)s * H1 + lane * 4];
    int* p = (int*)&pooled[(size_t)d * H1 + lane * 4];
    atomicMax(p + 0, __float_as_int(v.x));
    atomicMax(p + 1, __float_as_int(v.y));
    atomicMax(p + 2, __float_as_int(v.z));
    atomicMax(p + 3, __float_as_int(v.w));
}

// ---------------------------------------------------------------------------
// Head: out = sigmoid(h2 @ W2^T + b2), N_CLASSES=16, K=H2=256.
// Block = 256 threads = 16 nodes x 16 classes. W2 staged transposed in smem
// (Wt[k*16+c]) so LDS is conflict-free.
__global__ void __launch_bounds__(256) head_kernel(
    const float* __restrict__ h2, const float* __restrict__ W2,
    const float* __restrict__ b2, float* __restrict__ out)
{
    __shared__ float Wt[H2 * N_CLASSES];  // 16KB, transposed: [k][c]
    int tid = threadIdx.x;
    for (int i = tid; i < N_CLASSES * H2; i += 256) {
        int c = i / H2;
        int k = i % H2;
        Wt[k * N_CLASSES + c] = W2[i];
    }
    __syncthreads();

    int node = blockIdx.x * 16 + (tid >> 4);
    int c = tid & 15;
    const float* hrow = &h2[(size_t)node * H2];
    float s = 0.f;
#pragma unroll 8
    for (int k = 0; k < H2; k += 4) {
        float4 hv = *(const float4*)&hrow[k];
        s += hv.x * Wt[(k + 0) * N_CLASSES + c];
        s += hv.y * Wt[(k + 1) * N_CLASSES + c];
        s += hv.z * Wt[(k + 2) * N_CLASSES + c];
        s += hv.w * Wt[(k + 3) * N_CLASSES + c];
    }
    s += b2[c];
    out[(size_t)node * N_CLASSES + c] = 1.f / (1.f + expf(-s));
}

// ---------------------------------------------------------------------------
extern "C" void kernel_launch(void* const* d_in, const int* in_sizes, int n_in,
                              void* d_out, int out_size)
{
    const float* x  = (const float*)d_in[0];
    const float* Wp = (const float*)d_in[1];
    const float* bp = (const float*)d_in[2];
    const float* Ws = (const float*)d_in[3];
    const float* Wn = (const float*)d_in[4];
    const float* bn = (const float*)d_in[5];
    const float* W1 = (const float*)d_in[6];
    const float* b1 = (const float*)d_in[7];
    const float* W2 = (const float*)d_in[8];
    const float* b2 = (const float*)d_in[9];
    const int* src  = (const int*)d_in[10];
    const int* dst  = (const int*)d_in[11];
    float* out = (float*)d_out;

    float *y_p, *pooled_p, *h_p, *h2_p;
    cudaGetSymbolAddress((void**)&y_p, g_y);
    cudaGetSymbolAddress((void**)&pooled_p, g_pooled);
    cudaGetSymbolAddress((void**)&h_p, g_h);
    cudaGetSymbolAddress((void**)&h2_p, g_h2);

    // 1) pooled = 0
    zero_pooled_kernel<<<(N_NODES * H1 / 4 + 255) / 256, 256>>>(pooled_p);

    // 2) y = relu(x @ Wp^T + bp)   [N, 128]
    {
        dim3 grid(N_NODES / 128, H1 / 128);
        sgemm_kernel<1, false><<<grid, 256>>>(x, Wp, nullptr, nullptr, bp, y_p,
                                              N_NODES, H1, IN_FEATS);
    }

    // 3) pooled[d] = max over edges of y[s]
    {
        long long threads = (long long)N_EDGES * 32;
        scatter_max_kernel<<<(unsigned)((threads + 255) / 256), 256>>>(src, dst, y_p, pooled_p);
    }

    // 4) h = leaky_relu(x @ Ws^T + pooled @ Wn^T + bn)   [N, 128]
    {
        dim3 grid(N_NODES / 128, H1 / 128);
        sgemm_kernel<2, true><<<grid, 256>>>(x, Ws, pooled_p, Wn, bn, h_p,
                                             N_NODES, H1, IN_FEATS);
    }

    // 5) h2 = leaky_relu(h @ W1^T + b1)   [N, 256]
    {
        dim3 grid(N_NODES / 128, H2 / 128);
        sgemm_kernel<2, false><<<grid, 256>>>(h_p, W1, nullptr, nullptr, b1, h2_p,
                                              N_NODES, H2, H1);
    }

    // 6) out = sigmoid(h2 @ W2^T + b2)   [N, 16]
    head_kernel<<<N_NODES / 16, 256>>>(h2_p, W2, b2, out);
}

// round 3
// speedup vs baseline: 1.1741x; 1.1741x over previous
#include <cuda_runtime.h>
#include <math.h>

#define N_NODES 65536
#define N_EDGES 1048576
#define IN_FEATS 128
#define H1 128
#define H2 256
#define N_CLASSES 16

typedef unsigned long long ull;

// Scratch (allocation-free rule: __device__ globals)
__device__ float g_y[(size_t)N_NODES * H1];       // relu(x@Wp^T + bp)
__device__ float g_pooled[(size_t)N_NODES * H1];  // segment max
__device__ float g_h[(size_t)N_NODES * H1];       // after conv combine
__device__ float g_h2[(size_t)N_NODES * H2];      // after W1
__device__ int   g_deg[N_NODES];                  // in-degree histogram
__device__ int   g_off[N_NODES + 1];              // CSR offsets (by dst)
__device__ int   g_cursor[N_NODES];               // fill cursors
__device__ int   g_csr_src[N_EDGES];              // src ids grouped by dst

// ---------------------------------------------------------------------------
#define PACK_DUP_F32X2(out, v) \
    asm("mov.b64 %0, {%1, %1};" : "=l"(out) : "r"(__float_as_uint(v)))
#define UNPACK_F32X2_(lo, hi, in) \
    asm("mov.b64 {%0, %1}, %2;" : "=r"(lo), "=r"(hi) : "l"(in))
#define FMA_F32X2(d, a, b, c) \
    asm("fma.rn.f32x2 %0, %1, %2, %3;" : "=l"(d) : "l"(a), "l"(b), "l"(c))

// Activations: 0 = none, 1 = relu, 2 = leaky_relu(0.01)
template <int ACT>
__device__ __forceinline__ float act_fn(float v) {
    if (ACT == 1) return v > 0.f ? v : 0.f;
    if (ACT == 2) return v > 0.f ? v : 0.01f * v;
    return v;
}

// ---------------------------------------------------------------------------
__global__ void zero_deg_kernel(int* deg) {
    int i = blockIdx.x * blockDim.x + threadIdx.x;
    if (i < N_NODES) deg[i] = 0;
}

__global__ void hist_kernel(const int* __restrict__ dst, int* __restrict__ deg) {
    int e = blockIdx.x * blockDim.x + threadIdx.x;
    if (e < N_EDGES) atomicAdd(&deg[dst[e]], 1);
}

// Single-block exclusive scan over 65536 counts -> off + cursor.
__global__ void __launch_bounds__(1024) scan_kernel(
    const int* __restrict__ deg, int* __restrict__ off, int* __restrict__ cursor)
{
    __shared__ int sums[1024];
    const int PER = N_NODES / 1024;  // 64
    int tid = threadIdx.x;
    int base = tid * PER;
    int s = 0;
#pragma unroll 8
    for (int i = 0; i < PER; i++) s += deg[base + i];
    sums[tid] = s;
    __syncthreads();
    // Hillis-Steele inclusive scan
    for (int d = 1; d < 1024; d <<= 1) {
        int v = sums[tid];
        if (tid >= d) v += sums[tid - d];
        __syncthreads();
        sums[tid] = v;
        __syncthreads();
    }
    int run = sums[tid] - s;  // exclusive prefix
    for (int i = 0; i < PER; i++) {
        int d = deg[base + i];
        off[base + i] = run;
        cursor[base + i] = run;
        run += d;
    }
    if (tid == 1023) off[N_NODES] = run;
}

__global__ void fill_kernel(const int* __restrict__ src, const int* __restrict__ dst,
                            int* __restrict__ cursor, int* __restrict__ csr) {
    int e = blockIdx.x * blockDim.x + threadIdx.x;
    if (e < N_EDGES) {
        int p = atomicAdd(&cursor[dst[e]], 1);
        csr[p] = src[e];
    }
}

// One warp per node: pooled[n] = max over incoming edges of y[src], else 0.
__global__ void __launch_bounds__(256) pool_max_kernel(
    const int* __restrict__ off, const int* __restrict__ csr,
    const float* __restrict__ y, float* __restrict__ pooled)
{
    int warp = (blockIdx.x * blockDim.x + threadIdx.x) >> 5;
    if (warp >= N_NODES) return;
    int lane = threadIdx.x & 31;
    int beg = off[warp], end = off[warp + 1];
    float4 m = make_float4(0.f, 0.f, 0.f, 0.f);
    int e = beg;
    int sNext = (e < end) ? csr[e] : 0;
    while (e < end) {
        int s = sNext;
        ++e;
        if (e < end) sNext = csr[e];
        float4 v = *(const float4*)&y[(size_t)s * H1 + lane * 4];
        m.x = fmaxf(m.x, v.x);
        m.y = fmaxf(m.y, v.y);
        m.z = fmaxf(m.z, v.z);
        m.w = fmaxf(m.w, v.w);
    }
    *(float4*)&pooled[(size_t)warp * H1 + lane * 4] = m;
}

// ---------------------------------------------------------------------------
// SGEMM with packed fma.rn.f32x2:
// C[M,N] = act( A[M,K] @ B[N,K]^T  (+ A2@B2^T)  + bias[N] )
// BM=BN=128, BK=16, 256 threads, 8x8 per-thread microtile.
template <int ACT, bool HAS2>
__global__ void __launch_bounds__(256) sgemm_kernel(
    const float* __restrict__ A, const float* __restrict__ B,
    const float* __restrict__ A2, const float* __restrict__ B2,
    const float* __restrict__ bias, float* __restrict__ C,
    int M, int N, int K)
{
    const int BK = 16;
    __shared__ float As[BK][128];
    __shared__ float Bs[BK][128];

    const int m0 = blockIdx.x * 128;
    const int n0 = blockIdx.y * 128;
    const int tid = threadIdx.x;
    const int tx = tid & 15;
    const int ty = tid >> 4;

    // acc2[i2][j] holds rows (2*i2, 2*i2+1) packed as f32x2, column j.
    ull acc2[4][8];
#pragma unroll
    for (int i = 0; i < 4; i++)
#pragma unroll
        for (int j = 0; j < 8; j++) acc2[i][j] = 0ull;

    const int passes = HAS2 ? 2 : 1;
    for (int p = 0; p < passes; p++) {
        const float* Ap = (HAS2 && p == 1) ? A2 : A;
        const float* Bp = (HAS2 && p == 1) ? B2 : B;

        for (int k0 = 0; k0 < K; k0 += BK) {
#pragma unroll
            for (int it = 0; it < 2; it++) {
                int idx = tid + it * 256;     // 0..511
                int row = idx >> 2;           // 0..127
                int kc = idx & 3;             // float4 index in K
                float4 a = *(const float4*)&Ap[(size_t)(m0 + row) * K + k0 + kc * 4];
                As[kc * 4 + 0][row] = a.x;
                As[kc * 4 + 1][row] = a.y;
                As[kc * 4 + 2][row] = a.z;
                As[kc * 4 + 3][row] = a.w;
                float4 b = *(const float4*)&Bp[(size_t)(n0 + row) * K + k0 + kc * 4];
                Bs[kc * 4 + 0][row] = b.x;
                Bs[kc * 4 + 1][row] = b.y;
                Bs[kc * 4 + 2][row] = b.z;
                Bs[kc * 4 + 3][row] = b.w;
            }
            __syncthreads();

#pragma unroll
            for (int k = 0; k < BK; k++) {
                // A row-pairs: 8 consecutive floats -> 4 packed f32x2 (no MOVs).
                const ulonglong2* ap = (const ulonglong2*)&As[k][ty * 8];
                ulonglong2 a01 = ap[0];
                ulonglong2 a23 = ap[1];
                ull aP[4] = {a01.x, a01.y, a23.x, a23.y};

                float4 b0 = *(const float4*)&Bs[k][tx * 8];
                float4 b1 = *(const float4*)&Bs[k][tx * 8 + 4];
                ull bD[8];
                PACK_DUP_F32X2(bD[0], b0.x);
                PACK_DUP_F32X2(bD[1], b0.y);
                PACK_DUP_F32X2(bD[2], b0.z);
                PACK_DUP_F32X2(bD[3], b0.w);
                PACK_DUP_F32X2(bD[4], b1.x);
                PACK_DUP_F32X2(bD[5], b1.y);
                PACK_DUP_F32X2(bD[6], b1.z);
                PACK_DUP_F32X2(bD[7], b1.w);
#pragma unroll
                for (int i = 0; i < 4; i++)
#pragma unroll
                    for (int j = 0; j < 8; j++)
                        FMA_F32X2(acc2[i][j], aP[i], bD[j], acc2[i][j]);
            }
            __syncthreads();
        }
    }

    // Epilogue: unpack row pairs, add bias, activation, float4 stores.
#pragma unroll
    for (int i2 = 0; i2 < 4; i2++) {
        float lo[8], hi[8];
#pragma unroll
        for (int j = 0; j < 8; j++) {
            unsigned int ulo, uhi;
            UNPACK_F32X2_(ulo, uhi, acc2[i2][j]);
            lo[j] = __uint_as_float(ulo);
            hi[j] = __uint_as_float(uhi);
        }
        int row0 = m0 + ty * 8 + 2 * i2;
#pragma unroll
        for (int h = 0; h < 2; h++) {
            const float* v8 = h ? hi : lo;
            int row = row0 + h;
#pragma unroll
            for (int j = 0; j < 8; j += 4) {
                int col = n0 + tx * 8 + j;
                float4 v;
                v.x = act_fn<ACT>(v8[j + 0] + bias[col + 0]);
                v.y = act_fn<ACT>(v8[j + 1] + bias[col + 1]);
                v.z = act_fn<ACT>(v8[j + 2] + bias[col + 2]);
                v.w = act_fn<ACT>(v8[j + 3] + bias[col + 3]);
                *(float4*)&C[(size_t)row * N + col] = v;
            }
        }
    }
}

// ---------------------------------------------------------------------------
// Head: out = sigmoid(h2 @ W2^T + b2), N_CLASSES=16, K=H2=256.
__global__ void __launch_bounds__(256) head_kernel(
    const float* __restrict__ h2, const float* __restrict__ W2,
    const float* __restrict__ b2, float* __restrict__ out)
{
    __shared__ float Wt[H2 * N_CLASSES];  // transposed: [k][c]
    int tid = threadIdx.x;
    for (int i = tid; i < N_CLASSES * H2; i += 256) {
        int c = i / H2;
        int k = i % H2;
        Wt[k * N_CLASSES + c] = W2[i];
    }
    __syncthreads();

    int node = blockIdx.x * 16 + (tid >> 4);
    int c = tid & 15;
    const float* hrow = &h2[(size_t)node * H2];
    float s = 0.f;
#pragma unroll 8
    for (int k = 0; k < H2; k += 4) {
        float4 hv = *(const float4*)&hrow[k];
        s += hv.x * Wt[(k + 0) * N_CLASSES + c];
        s += hv.y * Wt[(k + 1) * N_CLASSES + c];
        s += hv.z * Wt[(k + 2) * N_CLASSES + c];
        s += hv.w * Wt[(k + 3) * N_CLASSES + c];
    }
    s += b2[c];
    out[(size_t)node * N_CLASSES + c] = 1.f / (1.f + expf(-s));
}

// ---------------------------------------------------------------------------
extern "C" void kernel_launch(void* const* d_in, const int* in_sizes, int n_in,
                              void* d_out, int out_size)
{
    const float* x  = (const float*)d_in[0];
    const float* Wp = (const float*)d_in[1];
    const float* bp = (const float*)d_in[2];
    const float* Ws = (const float*)d_in[3];
    const float* Wn = (const float*)d_in[4];
    const float* bn = (const float*)d_in[5];
    const float* W1 = (const float*)d_in[6];
    const float* b1 = (const float*)d_in[7];
    const float* W2 = (const float*)d_in[8];
    const float* b2 = (const float*)d_in[9];
    const int* src  = (const int*)d_in[10];
    const int* dst  = (const int*)d_in[11];
    float* out = (float*)d_out;

    float *y_p, *pooled_p, *h_p, *h2_p;
    int *deg_p, *off_p, *cur_p, *csr_p;
    cudaGetSymbolAddress((void**)&y_p, g_y);
    cudaGetSymbolAddress((void**)&pooled_p, g_pooled);
    cudaGetSymbolAddress((void**)&h_p, g_h);
    cudaGetSymbolAddress((void**)&h2_p, g_h2);
    cudaGetSymbolAddress((void**)&deg_p, g_deg);
    cudaGetSymbolAddress((void**)&off_p, g_off);
    cudaGetSymbolAddress((void**)&cur_p, g_cursor);
    cudaGetSymbolAddress((void**)&csr_p, g_csr_src);

    // CSR build (independent of y-GEMM; scheduler can overlap)
    zero_deg_kernel<<<N_NODES / 256, 256>>>(deg_p);
    hist_kernel<<<N_EDGES / 256, 256>>>(dst, deg_p);
    scan_kernel<<<1, 1024>>>(deg_p, off_p, cur_p);
    fill_kernel<<<N_EDGES / 256, 256>>>(src, dst, cur_p, csr_p);

    // y = relu(x @ Wp^T + bp)   [N, 128]
    {
        dim3 grid(N_NODES / 128, H1 / 128);
        sgemm_kernel<1, false><<<grid, 256>>>(x, Wp, nullptr, nullptr, bp, y_p,
                                              N_NODES, H1, IN_FEATS);
    }

    // pooled[n] = max over incoming edges of y[src]
    pool_max_kernel<<<N_NODES * 32 / 256, 256>>>(off_p, csr_p, y_p, pooled_p);

    // h = leaky_relu(x @ Ws^T + pooled @ Wn^T + bn)   [N, 128]
    {
        dim3 grid(N_NODES / 128, H1 / 128);
        sgemm_kernel<2, true><<<grid, 256>>>(x, Ws, pooled_p, Wn, bn, h_p,
                                             N_NODES, H1, IN_FEATS);
    }

    // h2 = leaky_relu(h @ W1^T + b1)   [N, 256]
    {
        dim3 grid(N_NODES / 128, H2 / 128);
        sgemm_kernel<2, false><<<grid, 256>>>(h_p, W1, nullptr, nullptr, b1, h2_p,
                                              N_NODES, H2, H1);
    }

    // out = sigmoid(h2 @ W2^T + b2)   [N, 16]
    head_kernel<<<N_NODES / 16, 256>>>(h2_p, W2, b2, out);
}

// round 5
// speedup vs baseline: 1.6317x; 1.3898x over previous
#include <cuda_runtime.h>
#include <math.h>
#include <stdint.h>

#define N_NODES 65536
#define N_EDGES 1048576
#define IN_FEATS 128
#define H1 128
#define H2 256
#define N_CLASSES 16

// Scratch (allocation-free rule: __device__ globals)
__device__ float g_y[(size_t)N_NODES * H1];
__device__ float g_pooled[(size_t)N_NODES * H1];
__device__ float g_h[(size_t)N_NODES * H1];
__device__ float g_h2[(size_t)N_NODES * H2];
__device__ int   g_deg[N_NODES];
__device__ int   g_off[N_NODES + 1];
__device__ int   g_cursor[N_NODES];
__device__ int   g_csr_src[N_EDGES];

// ---------------------------------------------------------------------------
__device__ __forceinline__ uint32_t f2tf32(float f) {
    uint32_t r;
    asm("cvt.rna.tf32.f32 %0, %1;" : "=r"(r) : "f"(f));
    return r;
}

__device__ __forceinline__ void mma_tf32(
    float& c0, float& c1, float& c2, float& c3,
    uint32_t a0, uint32_t a1, uint32_t a2, uint32_t a3,
    uint32_t b0, uint32_t b1)
{
    asm volatile(
        "mma.sync.aligned.m16n8k8.row.col.f32.tf32.tf32.f32 "
        "{%0,%1,%2,%3}, {%4,%5,%6,%7}, {%8,%9}, {%0,%1,%2,%3};"
        : "+f"(c0), "+f"(c1), "+f"(c2), "+f"(c3)
        : "r"(a0), "r"(a1), "r"(a2), "r"(a3), "r"(b0), "r"(b1));
}

// Activations: 0 = none, 1 = relu, 2 = leaky_relu(0.01)
template <int ACT>
__device__ __forceinline__ float act_fn(float v) {
    if (ACT == 1) return v > 0.f ? v : 0.f;
    if (ACT == 2) return v > 0.f ? v : 0.01f * v;
    return v;
}

// ---------------------------------------------------------------------------
// Stage a 128x128 fp32 tile (row-major, ld=128) into smem as tf32, stride 132.
__device__ __forceinline__ void stage_tile(
    uint32_t* __restrict__ s, const float* __restrict__ gtile, int tid)
{
    const float4* g4 = (const float4*)gtile;
#pragma unroll
    for (int it = 0; it < 16; it++) {
        int i = tid + it * 256;        // 0..4095
        int row = i >> 5;
        int c4 = i & 31;
        float4 v = g4[row * 32 + c4];
        uint4 t;
        t.x = f2tf32(v.x);
        t.y = f2tf32(v.y);
        t.z = f2tf32(v.z);
        t.w = f2tf32(v.w);
        *(uint4*)&s[row * 132 + c4 * 4] = t;   // 132*4 B rows keep 16B alignment
    }
}

// ---------------------------------------------------------------------------
// tf32 mma.sync GEMM: C[M,N] = act( A[M,128] @ B[N,128]^T (+ A2@B2^T) + bias )
// CTA tile 128x128, 256 threads (8 warps, 2x4), warp tile 64x32.
template <int N, int ACT, bool DUAL>
__global__ void __launch_bounds__(256) mma_gemm_kernel(
    const float* __restrict__ A, const float* __restrict__ B,
    const float* __restrict__ A2, const float* __restrict__ B2,
    const float* __restrict__ bias, float* __restrict__ C)
{
    extern __shared__ uint32_t smem[];
    uint32_t* As = smem;                 // [128][132]
    uint32_t* Bs = smem + 128 * 132;     // [128][132]

    const int tid = threadIdx.x;
    const int lane = tid & 31;
    const int wid = tid >> 5;
    const int wm = wid >> 2;             // 0..1  (64-row slabs)
    const int wn = wid & 3;              // 0..3  (32-col slabs)
    const int g = lane >> 2;             // 0..7
    const int t4 = lane & 3;             // 0..3
    const int m0 = blockIdx.x * 128;
    const int n0 = blockIdx.y * 128;

    float acc[4][4][4];
#pragma unroll
    for (int mt = 0; mt < 4; mt++)
#pragma unroll
        for (int nt = 0; nt < 4; nt++)
#pragma unroll
            for (int r = 0; r < 4; r++) acc[mt][nt][r] = 0.f;

    const int passes = DUAL ? 2 : 1;
    for (int p = 0; p < passes; p++) {
        const float* Ap = (DUAL && p == 1) ? A2 : A;
        const float* Bp = (DUAL && p == 1) ? B2 : B;
        if (p == 1) __syncthreads();     // all warps done reading pass-1 tiles
        stage_tile(As, Ap + (size_t)m0 * 128, tid);
        stage_tile(Bs, Bp + (size_t)n0 * 128, tid);
        __syncthreads();

#pragma unroll 1
        for (int ks = 0; ks < 16; ks++) {
            const int k0 = ks * 8;
            uint32_t bf[4][2];
#pragma unroll
            for (int nt = 0; nt < 4; nt++) {
                int n = wn * 32 + nt * 8 + g;
                bf[nt][0] = Bs[n * 132 + k0 + t4];
                bf[nt][1] = Bs[n * 132 + k0 + 4 + t4];
            }
#pragma unroll
            for (int mt = 0; mt < 4; mt++) {
                int m = wm * 64 + mt * 16 + g;
                uint32_t a0 = As[m * 132 + k0 + t4];
                uint32_t a1 = As[(m + 8) * 132 + k0 + t4];
                uint32_t a2 = As[m * 132 + k0 + 4 + t4];
                uint32_t a3 = As[(m + 8) * 132 + k0 + 4 + t4];
#pragma unroll
                for (int nt = 0; nt < 4; nt++)
                    mma_tf32(acc[mt][nt][0], acc[mt][nt][1], acc[mt][nt][2], acc[mt][nt][3],
                             a0, a1, a2, a3, bf[nt][0], bf[nt][1]);
            }
        }
    }

    // Epilogue: c0/c1 at (row, 2t4/2t4+1), c2/c3 at (row+8, ...)
#pragma unroll
    for (int mt = 0; mt < 4; mt++) {
        int row = m0 + wm * 64 + mt * 16 + g;
#pragma unroll
        for (int nt = 0; nt < 4; nt++) {
            int col = n0 + wn * 32 + nt * 8 + 2 * t4;
            float bv0 = __ldg(&bias[col]);
            float bv1 = __ldg(&bias[col + 1]);
            float2 v0, v1;
            v0.x = act_fn<ACT>(acc[mt][nt][0] + bv0);
            v0.y = act_fn<ACT>(acc[mt][nt][1] + bv1);
            v1.x = act_fn<ACT>(acc[mt][nt][2] + bv0);
            v1.y = act_fn<ACT>(acc[mt][nt][3] + bv1);
            *(float2*)&C[(size_t)row * N + col] = v0;
            *(float2*)&C[(size_t)(row + 8) * N + col] = v1;
        }
    }
}

// ---------------------------------------------------------------------------
// Edge-phase kernels
__global__ void zero_deg_kernel(int* deg) {
    int i = blockIdx.x * blockDim.x + threadIdx.x;
    if (i < N_NODES) deg[i] = 0;
}

__global__ void hist_kernel(const int* __restrict__ dst, int* __restrict__ deg) {
    int e = blockIdx.x * blockDim.x + threadIdx.x;
    if (e < N_EDGES) atomicAdd(&deg[dst[e]], 1);
}

__global__ void __launch_bounds__(1024) scan_kernel(
    const int* __restrict__ deg, int* __restrict__ off, int* __restrict__ cursor)
{
    __shared__ int sums[1024];
    const int PER = N_NODES / 1024;
    int tid = threadIdx.x;
    int base = tid * PER;
    int s = 0;
#pragma unroll 8
    for (int i = 0; i < PER; i++) s += deg[base + i];
    sums[tid] = s;
    __syncthreads();
    for (int d = 1; d < 1024; d <<= 1) {
        int v = sums[tid];
        if (tid >= d) v += sums[tid - d];
        __syncthreads();
        sums[tid] = v;
        __syncthreads();
    }
    int run = sums[tid] - s;
    for (int i = 0; i < PER; i++) {
        int d = deg[base + i];
        off[base + i] = run;
        cursor[base + i] = run;
        run += d;
    }
    if (tid == 1023) off[N_NODES] = run;
}

__global__ void fill_kernel(const int* __restrict__ src, const int* __restrict__ dst,
                            int* __restrict__ cursor, int* __restrict__ csr) {
    int e = blockIdx.x * blockDim.x + threadIdx.x;
    if (e < N_EDGES) {
        int p = atomicAdd(&cursor[dst[e]], 1);
        csr[p] = src[e];
    }
}

__global__ void __launch_bounds__(256) pool_max_kernel(
    const int* __restrict__ off, const int* __restrict__ csr,
    const float* __restrict__ y, float* __restrict__ pooled)
{
    int warp = (blockIdx.x * blockDim.x + threadIdx.x) >> 5;
    if (warp >= N_NODES) return;
    int lane = threadIdx.x & 31;
    int beg = off[warp], end = off[warp + 1];
    float4 m = make_float4(0.f, 0.f, 0.f, 0.f);
    int e = beg;
    int sNext = (e < end) ? csr[e] : 0;
    while (e < end) {
        int s = sNext;
        ++e;
        if (e < end) sNext = csr[e];
        float4 v = *(const float4*)&y[(size_t)s * H1 + lane * 4];
        m.x = fmaxf(m.x, v.x);
        m.y = fmaxf(m.y, v.y);
        m.z = fmaxf(m.z, v.z);
        m.w = fmaxf(m.w, v.w);
    }
    *(float4*)&pooled[(size_t)warp * H1 + lane * 4] = m;
}

// ---------------------------------------------------------------------------
__global__ void __launch_bounds__(256) head_kernel(
    const float* __restrict__ h2, const float* __restrict__ W2,
    const float* __restrict__ b2, float* __restrict__ out)
{
    __shared__ float Wt[H2 * N_CLASSES];
    int tid = threadIdx.x;
    for (int i = tid; i < N_CLASSES * H2; i += 256) {
        int c = i / H2;
        int k = i % H2;
        Wt[k * N_CLASSES + c] = W2[i];
    }
    __syncthreads();

    int node = blockIdx.x * 16 + (tid >> 4);
    int c = tid & 15;
    const float* hrow = &h2[(size_t)node * H2];
    float s = 0.f;
#pragma unroll 8
    for (int k = 0; k < H2; k += 4) {
        float4 hv = *(const float4*)&hrow[k];
        s += hv.x * Wt[(k + 0) * N_CLASSES + c];
        s += hv.y * Wt[(k + 1) * N_CLASSES + c];
        s += hv.z * Wt[(k + 2) * N_CLASSES + c];
        s += hv.w * Wt[(k + 3) * N_CLASSES + c];
    }
    s += b2[c];
    out[(size_t)node * N_CLASSES + c] = 1.f / (1.f + expf(-s));
}

// ---------------------------------------------------------------------------
extern "C" void kernel_launch(void* const* d_in, const int* in_sizes, int n_in,
                              void* d_out, int out_size)
{
    const float* x  = (const float*)d_in[0];
    const float* Wp = (const float*)d_in[1];
    const float* bp = (const float*)d_in[2];
    const float* Ws = (const float*)d_in[3];
    const float* Wn = (const float*)d_in[4];
    const float* bn = (const float*)d_in[5];
    const float* W1 = (const float*)d_in[6];
    const float* b1 = (const float*)d_in[7];
    const float* W2 = (const float*)d_in[8];
    const float* b2 = (const float*)d_in[9];
    const int* src  = (const int*)d_in[10];
    const int* dst  = (const int*)d_in[11];
    float* out = (float*)d_out;

    float *y_p, *pooled_p, *h_p, *h2_p;
    int *deg_p, *off_p, *cur_p, *csr_p;
    cudaGetSymbolAddress((void**)&y_p, g_y);
    cudaGetSymbolAddress((void**)&pooled_p, g_pooled);
    cudaGetSymbolAddress((void**)&h_p, g_h);
    cudaGetSymbolAddress((void**)&h2_p, g_h2);
    cudaGetSymbolAddress((void**)&deg_p, g_deg);
    cudaGetSymbolAddress((void**)&off_p, g_off);
    cudaGetSymbolAddress((void**)&cur_p, g_cursor);
    cudaGetSymbolAddress((void**)&csr_p, g_csr_src);

    const int SMEM = 2 * 128 * 132 * 4;  // 135168 B dynamic
    cudaFuncSetAttribute(mma_gemm_kernel<128, 1, false>,
                         cudaFuncAttributeMaxDynamicSharedMemorySize, SMEM);
    cudaFuncSetAttribute(mma_gemm_kernel<128, 2, true>,
                         cudaFuncAttributeMaxDynamicSharedMemorySize, SMEM);
    cudaFuncSetAttribute(mma_gemm_kernel<256, 2, false>,
                         cudaFuncAttributeMaxDynamicSharedMemorySize, SMEM);

    // CSR build
    zero_deg_kernel<<<N_NODES / 256, 256>>>(deg_p);
    hist_kernel<<<N_EDGES / 256, 256>>>(dst, deg_p);
    scan_kernel<<<1, 1024>>>(deg_p, off_p, cur_p);
    fill_kernel<<<N_EDGES / 256, 256>>>(src, dst, cur_p, csr_p);

    // y = relu(x @ Wp^T + bp)
    mma_gemm_kernel<128, 1, false><<<dim3(N_NODES / 128, 1), 256, SMEM>>>(
        x, Wp, nullptr, nullptr, bp, y_p);

    // pooled[n] = max over incoming edges of y[src]
    pool_max_kernel<<<N_NODES * 32 / 256, 256>>>(off_p, csr_p, y_p, pooled_p);

    // h = leaky_relu(x @ Ws^T + pooled @ Wn^T + bn)
    mma_gemm_kernel<128, 2, true><<<dim3(N_NODES / 128, 1), 256, SMEM>>>(
        x, Ws, pooled_p, Wn, bn, h_p);

    // h2 = leaky_relu(h @ W1^T + b1)
    mma_gemm_kernel<256, 2, false><<<dim3(N_NODES / 128, 2), 256, SMEM>>>(
        h_p, W1, nullptr, nullptr, b1, h2_p);

    // out = sigmoid(h2 @ W2^T + b2)
    head_kernel<<<N_NODES / 16, 256>>>(h2_p, W2, b2, out);
}

// round 6
// speedup vs baseline: 1.7148x; 1.0509x over previous
#include <cuda_runtime.h>
#include <math.h>
#include <stdint.h>

#define N_NODES 65536
#define N_EDGES 1048576
#define IN_FEATS 128
#define H1 128
#define H2 256
#define N_CLASSES 16

// Scratch (allocation-free rule: __device__ globals)
__device__ float g_y[(size_t)N_NODES * H1];
__device__ float g_pooled[(size_t)N_NODES * H1];
__device__ float g_h[(size_t)N_NODES * H1];
__device__ float g_h2[(size_t)N_NODES * H2];
__device__ int   g_deg[N_NODES];
__device__ int   g_off[N_NODES + 1];
__device__ int   g_cursor[N_NODES];
__device__ int   g_csr_src[N_EDGES];

// ---------------------------------------------------------------------------
__device__ __forceinline__ void mma_tf32(
    float& c0, float& c1, float& c2, float& c3,
    uint32_t a0, uint32_t a1, uint32_t a2, uint32_t a3,
    uint32_t b0, uint32_t b1)
{
    asm volatile(
        "mma.sync.aligned.m16n8k8.row.col.f32.tf32.tf32.f32 "
        "{%0,%1,%2,%3}, {%4,%5,%6,%7}, {%8,%9}, {%0,%1,%2,%3};"
        : "+f"(c0), "+f"(c1), "+f"(c2), "+f"(c3)
        : "r"(a0), "r"(a1), "r"(a2), "r"(a3), "r"(b0), "r"(b1));
}

#define CP_COMMIT() asm volatile("cp.async.commit_group;" ::: "memory")
#define CP_WAIT0()  asm volatile("cp.async.wait_group 0;" ::: "memory")

// Activations: 0 = none, 1 = relu, 2 = leaky_relu(0.01)
template <int ACT>
__device__ __forceinline__ float act_fn(float v) {
    if (ACT == 1) return v > 0.f ? v : 0.f;
    if (ACT == 2) return v > 0.f ? v : 0.01f * v;
    return v;
}

// ---------------------------------------------------------------------------
// Stage ROWS x 128 fp32 tile (row-major, ld=128) into smem (stride 132 words)
// via cp.async 16B copies. Raw fp32 bits; tf32 MMA truncates mantissa in HW.
template <int ROWS, int THREADS>
__device__ __forceinline__ void stage_async(
    uint32_t* __restrict__ s, const float* __restrict__ gtile, int tid)
{
    const float4* g4 = (const float4*)gtile;
#pragma unroll
    for (int it = 0; it < ROWS * 32 / THREADS; it++) {
        int i = tid + it * THREADS;
        int row = i >> 5;
        int c4 = i & 31;
        uint32_t sa = (uint32_t)__cvta_generic_to_shared(&s[row * 132 + c4 * 4]);
        asm volatile("cp.async.ca.shared.global [%0], [%1], 16;"
                     :: "r"(sa), "l"(g4 + i) : "memory");
    }
}

// ---------------------------------------------------------------------------
// tf32 mma.sync GEMM: C[M,BN] = act( A[M,128] @ B[BN,128]^T (+ A2@B2^T) + bias )
// CTA tile 128 x BN. BN=128 -> 256 thr (8 warps 2x4). BN=256 -> 512 thr (2x8).
// Warp tile 64x32 in both cases.
template <int BN, int ACT, bool DUAL>
__global__ void __launch_bounds__(BN * 2) mma_gemm_kernel(
    const float* __restrict__ A, const float* __restrict__ B,
    const float* __restrict__ A2, const float* __restrict__ B2,
    const float* __restrict__ bias, float* __restrict__ C)
{
    const int THREADS = BN * 2;
    const int WN = BN / 32;              // warp columns (4 or 8)
    extern __shared__ uint32_t smem[];
    uint32_t* As = smem;                 // [128][132]
    uint32_t* Bs = smem + 128 * 132;     // [BN][132]

    const int tid = threadIdx.x;
    const int lane = tid & 31;
    const int wid = tid >> 5;
    const int wn = wid & (WN - 1);
    const int wm = wid / WN;             // 0..1
    const int g = lane >> 2;             // 0..7
    const int t4 = lane & 3;             // 0..3
    const int m0 = blockIdx.x * 128;

    float acc[4][4][4];
#pragma unroll
    for (int mt = 0; mt < 4; mt++)
#pragma unroll
        for (int nt = 0; nt < 4; nt++)
#pragma unroll
            for (int r = 0; r < 4; r++) acc[mt][nt][r] = 0.f;

    const int passes = DUAL ? 2 : 1;
    for (int p = 0; p < passes; p++) {
        const float* Ap = (DUAL && p == 1) ? A2 : A;
        const float* Bp = (DUAL && p == 1) ? B2 : B;
        if (p == 1) __syncthreads();     // all warps done reading pass-1 tiles
        stage_async<128, THREADS>(As, Ap + (size_t)m0 * 128, tid);
        stage_async<BN, THREADS>(Bs, Bp, tid);
        CP_COMMIT();
        CP_WAIT0();
        __syncthreads();

#pragma unroll 1
        for (int ks = 0; ks < 16; ks++) {
            const int k0 = ks * 8;
            uint32_t bf[4][2];
#pragma unroll
            for (int nt = 0; nt < 4; nt++) {
                int n = wn * 32 + nt * 8 + g;
                bf[nt][0] = Bs[n * 132 + k0 + t4];
                bf[nt][1] = Bs[n * 132 + k0 + 4 + t4];
            }
#pragma unroll
            for (int mt = 0; mt < 4; mt++) {
                int m = wm * 64 + mt * 16 + g;
                uint32_t a0 = As[m * 132 + k0 + t4];
                uint32_t a1 = As[(m + 8) * 132 + k0 + t4];
                uint32_t a2 = As[m * 132 + k0 + 4 + t4];
                uint32_t a3 = As[(m + 8) * 132 + k0 + 4 + t4];
#pragma unroll
                for (int nt = 0; nt < 4; nt++)
                    mma_tf32(acc[mt][nt][0], acc[mt][nt][1], acc[mt][nt][2], acc[mt][nt][3],
                             a0, a1, a2, a3, bf[nt][0], bf[nt][1]);
            }
        }
    }

    // Epilogue
#pragma unroll
    for (int mt = 0; mt < 4; mt++) {
        int row = m0 + wm * 64 + mt * 16 + g;
#pragma unroll
        for (int nt = 0; nt < 4; nt++) {
            int col = wn * 32 + nt * 8 + 2 * t4;
            float bv0 = __ldg(&bias[col]);
            float bv1 = __ldg(&bias[col + 1]);
            float2 v0, v1;
            v0.x = act_fn<ACT>(acc[mt][nt][0] + bv0);
            v0.y = act_fn<ACT>(acc[mt][nt][1] + bv1);
            v1.x = act_fn<ACT>(acc[mt][nt][2] + bv0);
            v1.y = act_fn<ACT>(acc[mt][nt][3] + bv1);
            *(float2*)&C[(size_t)row * BN + col] = v0;
            *(float2*)&C[(size_t)(row + 8) * BN + col] = v1;
        }
    }
}

// ---------------------------------------------------------------------------
// Edge-phase kernels
__global__ void hist_kernel(const int* __restrict__ dst, int* __restrict__ deg) {
    int e = blockIdx.x * blockDim.x + threadIdx.x;
    if (e < N_EDGES) atomicAdd(&deg[dst[e]], 1);
}

__global__ void __launch_bounds__(1024) scan_kernel(
    const int* __restrict__ deg, int* __restrict__ off, int* __restrict__ cursor)
{
    __shared__ int sums[1024];
    const int PER = N_NODES / 1024;
    int tid = threadIdx.x;
    int base = tid * PER;
    int s = 0;
#pragma unroll 8
    for (int i = 0; i < PER; i++) s += deg[base + i];
    sums[tid] = s;
    __syncthreads();
    for (int d = 1; d < 1024; d <<= 1) {
        int v = sums[tid];
        if (tid >= d) v += sums[tid - d];
        __syncthreads();
        sums[tid] = v;
        __syncthreads();
    }
    int run = sums[tid] - s;
    for (int i = 0; i < PER; i++) {
        int d = deg[base + i];
        off[base + i] = run;
        cursor[base + i] = run;
        run += d;
    }
    if (tid == 1023) off[N_NODES] = run;
}

__global__ void fill_kernel(const int* __restrict__ src, const int* __restrict__ dst,
                            int* __restrict__ cursor, int* __restrict__ csr) {
    int e = blockIdx.x * blockDim.x + threadIdx.x;
    if (e < N_EDGES) {
        int p = atomicAdd(&cursor[dst[e]], 1);
        csr[p] = src[e];
    }
}

__device__ __forceinline__ void max4(float4& m, float4 v) {
    m.x = fmaxf(m.x, v.x);
    m.y = fmaxf(m.y, v.y);
    m.z = fmaxf(m.z, v.z);
    m.w = fmaxf(m.w, v.w);
}

// One warp per node, 4 edges in flight for MLP.
__global__ void __launch_bounds__(256) pool_max_kernel(
    const int* __restrict__ off, const int* __restrict__ csr,
    const float* __restrict__ y, float* __restrict__ pooled)
{
    int warp = (blockIdx.x * blockDim.x + threadIdx.x) >> 5;
    if (warp >= N_NODES) return;
    int lane = threadIdx.x & 31;
    int beg = off[warp], end = off[warp + 1];
    float4 m = make_float4(0.f, 0.f, 0.f, 0.f);
    int e = beg;
    for (; e + 4 <= end; e += 4) {
        int s0 = __ldg(&csr[e + 0]);
        int s1 = __ldg(&csr[e + 1]);
        int s2 = __ldg(&csr[e + 2]);
        int s3 = __ldg(&csr[e + 3]);
        float4 v0 = *(const float4*)&y[(size_t)s0 * H1 + lane * 4];
        float4 v1 = *(const float4*)&y[(size_t)s1 * H1 + lane * 4];
        float4 v2 = *(const float4*)&y[(size_t)s2 * H1 + lane * 4];
        float4 v3 = *(const float4*)&y[(size_t)s3 * H1 + lane * 4];
        max4(m, v0);
        max4(m, v1);
        max4(m, v2);
        max4(m, v3);
    }
    for (; e < end; e++) {
        int s = __ldg(&csr[e]);
        float4 v = *(const float4*)&y[(size_t)s * H1 + lane * 4];
        max4(m, v);
    }
    *(float4*)&pooled[(size_t)warp * H1 + lane * 4] = m;
}

// ---------------------------------------------------------------------------
__global__ void __launch_bounds__(256) head_kernel(
    const float* __restrict__ h2, const float* __restrict__ W2,
    const float* __restrict__ b2, float* __restrict__ out)
{
    __shared__ float Wt[H2 * N_CLASSES];
    int tid = threadIdx.x;
    for (int i = tid; i < N_CLASSES * H2; i += 256) {
        int c = i / H2;
        int k = i % H2;
        Wt[k * N_CLASSES + c] = W2[i];
    }
    __syncthreads();

    int node = blockIdx.x * 16 + (tid >> 4);
    int c = tid & 15;
    const float* hrow = &h2[(size_t)node * H2];
    float s = 0.f;
#pragma unroll 8
    for (int k = 0; k < H2; k += 4) {
        float4 hv = *(const float4*)&hrow[k];
        s += hv.x * Wt[(k + 0) * N_CLASSES + c];
        s += hv.y * Wt[(k + 1) * N_CLASSES + c];
        s += hv.z * Wt[(k + 2) * N_CLASSES + c];
        s += hv.w * Wt[(k + 3) * N_CLASSES + c];
    }
    s += b2[c];
    out[(size_t)node * N_CLASSES + c] = 1.f / (1.f + expf(-s));
}

// ---------------------------------------------------------------------------
extern "C" void kernel_launch(void* const* d_in, const int* in_sizes, int n_in,
                              void* d_out, int out_size)
{
    const float* x  = (const float*)d_in[0];
    const float* Wp = (const float*)d_in[1];
    const float* bp = (const float*)d_in[2];
    const float* Ws = (const float*)d_in[3];
    const float* Wn = (const float*)d_in[4];
    const float* bn = (const float*)d_in[5];
    const float* W1 = (const float*)d_in[6];
    const float* b1 = (const float*)d_in[7];
    const float* W2 = (const float*)d_in[8];
    const float* b2 = (const float*)d_in[9];
    const int* src  = (const int*)d_in[10];
    const int* dst  = (const int*)d_in[11];
    float* out = (float*)d_out;

    float *y_p, *pooled_p, *h_p, *h2_p;
    int *deg_p, *off_p, *cur_p, *csr_p;
    cudaGetSymbolAddress((void**)&y_p, g_y);
    cudaGetSymbolAddress((void**)&pooled_p, g_pooled);
    cudaGetSymbolAddress((void**)&h_p, g_h);
    cudaGetSymbolAddress((void**)&h2_p, g_h2);
    cudaGetSymbolAddress((void**)&deg_p, g_deg);
    cudaGetSymbolAddress((void**)&off_p, g_off);
    cudaGetSymbolAddress((void**)&cur_p, g_cursor);
    cudaGetSymbolAddress((void**)&csr_p, g_csr_src);

    const int SMEM_128 = (128 + 128) * 132 * 4;  // 135168 B
    const int SMEM_256 = (128 + 256) * 132 * 4;  // 202752 B
    cudaFuncSetAttribute(mma_gemm_kernel<128, 1, false>,
                         cudaFuncAttributeMaxDynamicSharedMemorySize, SMEM_128);
    cudaFuncSetAttribute(mma_gemm_kernel<128, 2, true>,
                         cudaFuncAttributeMaxDynamicSharedMemorySize, SMEM_128);
    cudaFuncSetAttribute(mma_gemm_kernel<256, 2, false>,
                         cudaFuncAttributeMaxDynamicSharedMemorySize, SMEM_256);

    // CSR build
    cudaMemsetAsync(deg_p, 0, N_NODES * sizeof(int));
    hist_kernel<<<N_EDGES / 256, 256>>>(dst, deg_p);
    scan_kernel<<<1, 1024>>>(deg_p, off_p, cur_p);
    fill_kernel<<<N_EDGES / 256, 256>>>(src, dst, cur_p, csr_p);

    // y = relu(x @ Wp^T + bp)
    mma_gemm_kernel<128, 1, false><<<N_NODES / 128, 256, SMEM_128>>>(
        x, Wp, nullptr, nullptr, bp, y_p);

    // pooled[n] = max over incoming edges of y[src]
    pool_max_kernel<<<N_NODES * 32 / 256, 256>>>(off_p, csr_p, y_p, pooled_p);

    // h = leaky_relu(x @ Ws^T + pooled @ Wn^T + bn)
    mma_gemm_kernel<128, 2, true><<<N_NODES / 128, 256, SMEM_128>>>(
        x, Ws, pooled_p, Wn, bn, h_p);

    // h2 = leaky_relu(h @ W1^T + b1)  — one 128x256 tile per CTA, 512 threads
    mma_gemm_kernel<256, 2, false><<<N_NODES / 128, 512, SMEM_256>>>(
        h_p, W1, nullptr, nullptr, b1, h2_p);

    // out = sigmoid(h2 @ W2^T + b2)
    head_kernel<<<N_NODES / 16, 256>>>(h2_p, W2, b2, out);
}

// round 7
// speedup vs baseline: 2.5016x; 1.4588x over previous
#include <cuda_runtime.h>
#include <math.h>
#include <stdint.h>

#define N_NODES 65536
#define N_EDGES 1048576
#define IN_FEATS 128
#define H1 128
#define H2 256
#define N_CLASSES 16

// Scratch (allocation-free rule: __device__ globals)
__device__ float g_ys[(size_t)N_NODES * 256];     // [y | s] interleaved rows
__device__ float g_pooled[(size_t)N_NODES * H1];
__device__ float g_h[(size_t)N_NODES * H1];
__device__ float g_h2[(size_t)N_NODES * H2];
__device__ int   g_deg[N_NODES + 1];              // [N_NODES] = global cursor
__device__ int   g_off[N_NODES];
__device__ int   g_cursor[N_NODES];
__device__ int   g_csr_src[N_EDGES];

// ---------------------------------------------------------------------------
__device__ __forceinline__ void mma_tf32(
    float& c0, float& c1, float& c2, float& c3,
    uint32_t a0, uint32_t a1, uint32_t a2, uint32_t a3,
    uint32_t b0, uint32_t b1)
{
    asm volatile(
        "mma.sync.aligned.m16n8k8.row.col.f32.tf32.tf32.f32 "
        "{%0,%1,%2,%3}, {%4,%5,%6,%7}, {%8,%9}, {%0,%1,%2,%3};"
        : "+f"(c0), "+f"(c1), "+f"(c2), "+f"(c3)
        : "r"(a0), "r"(a1), "r"(a2), "r"(a3), "r"(b0), "r"(b1));
}

#define CP_COMMIT() asm volatile("cp.async.commit_group;" ::: "memory")
#define CP_WAIT0()  asm volatile("cp.async.wait_group 0;" ::: "memory")

template <int ACT>
__device__ __forceinline__ float act_fn(float v) {
    if (ACT == 1) return v > 0.f ? v : 0.f;
    if (ACT == 2) return v > 0.f ? v : 0.01f * v;
    return v;
}

// Stage ROWS x 128 fp32 tile (row-major, ld=128) into smem (stride 132 words)
// via cp.async 16B copies. Raw fp32 bits; tf32 MMA truncates mantissa in HW.
template <int ROWS, int THREADS>
__device__ __forceinline__ void stage_async(
    uint32_t* __restrict__ s, const float* __restrict__ gtile, int tid)
{
    const float4* g4 = (const float4*)gtile;
#pragma unroll
    for (int it = 0; it < ROWS * 32 / THREADS; it++) {
        int i = tid + it * THREADS;
        int row = i >> 5;
        int c4 = i & 31;
        uint32_t sa = (uint32_t)__cvta_generic_to_shared(&s[row * 132 + c4 * 4]);
        asm volatile("cp.async.ca.shared.global [%0], [%1], 16;"
                     :: "r"(sa), "l"(g4 + i) : "memory");
    }
}

// Shared warp-tile mainloop: 64x32 warp tile over K=128, As [128][132], Bs [BN][132].
__device__ __forceinline__ void mma_mainloop(
    const uint32_t* __restrict__ As, const uint32_t* __restrict__ Bs,
    float acc[4][4][4], int wm, int wn, int g, int t4)
{
#pragma unroll 1
    for (int ks = 0; ks < 16; ks++) {
        const int k0 = ks * 8;
        uint32_t bf[4][2];
#pragma unroll
        for (int nt = 0; nt < 4; nt++) {
            int n = wn * 32 + nt * 8 + g;
            bf[nt][0] = Bs[n * 132 + k0 + t4];
            bf[nt][1] = Bs[n * 132 + k0 + 4 + t4];
        }
#pragma unroll
        for (int mt = 0; mt < 4; mt++) {
            int m = wm * 64 + mt * 16 + g;
            uint32_t a0 = As[m * 132 + k0 + t4];
            uint32_t a1 = As[(m + 8) * 132 + k0 + t4];
            uint32_t a2 = As[m * 132 + k0 + 4 + t4];
            uint32_t a3 = As[(m + 8) * 132 + k0 + 4 + t4];
#pragma unroll
            for (int nt = 0; nt < 4; nt++)
                mma_tf32(acc[mt][nt][0], acc[mt][nt][1], acc[mt][nt][2], acc[mt][nt][3],
                         a0, a1, a2, a3, bf[nt][0], bf[nt][1]);
        }
    }
}

// ---------------------------------------------------------------------------
// GEMM1 fused: ys[row, 0:128]   = relu(x @ Wp^T + bp)   (y, feeds pooling)
//              ys[row, 128:256] = x @ Ws^T + bn          (s, self term)
// CTA 128x256, 512 threads (16 warps, 2x8).
__global__ void __launch_bounds__(512) gemm1_fused_kernel(
    const float* __restrict__ x, const float* __restrict__ Wp,
    const float* __restrict__ Ws, const float* __restrict__ bp,
    const float* __restrict__ bn, float* __restrict__ ys)
{
    extern __shared__ uint32_t smem[];
    uint32_t* As = smem;                 // [128][132]
    uint32_t* Bs = smem + 128 * 132;     // [256][132]

    const int tid = threadIdx.x;
    const int lane = tid & 31;
    const int wid = tid >> 5;
    const int wn = wid & 7;
    const int wm = wid >> 3;
    const int g = lane >> 2;
    const int t4 = lane & 3;
    const int m0 = blockIdx.x * 128;

    float acc[4][4][4];
#pragma unroll
    for (int mt = 0; mt < 4; mt++)
#pragma unroll
        for (int nt = 0; nt < 4; nt++)
#pragma unroll
            for (int r = 0; r < 4; r++) acc[mt][nt][r] = 0.f;

    stage_async<128, 512>(As, x + (size_t)m0 * 128, tid);
    stage_async<128, 512>(Bs, Wp, tid);
    stage_async<128, 512>(Bs + 128 * 132, Ws, tid);
    CP_COMMIT();
    CP_WAIT0();
    __syncthreads();

    mma_mainloop(As, Bs, acc, wm, wn, g, t4);

    const bool is_y = (wn < 4);
#pragma unroll
    for (int mt = 0; mt < 4; mt++) {
        int row = m0 + wm * 64 + mt * 16 + g;
#pragma unroll
        for (int nt = 0; nt < 4; nt++) {
            int col = wn * 32 + nt * 8 + 2 * t4;      // 0..255
            float bv0, bv1;
            if (is_y) { bv0 = __ldg(&bp[col]); bv1 = __ldg(&bp[col + 1]); }
            else      { bv0 = __ldg(&bn[col - 128]); bv1 = __ldg(&bn[col - 127]); }
            float2 v0, v1;
            if (is_y) {
                v0.x = act_fn<1>(acc[mt][nt][0] + bv0);
                v0.y = act_fn<1>(acc[mt][nt][1] + bv1);
                v1.x = act_fn<1>(acc[mt][nt][2] + bv0);
                v1.y = act_fn<1>(acc[mt][nt][3] + bv1);
            } else {
                v0.x = acc[mt][nt][0] + bv0;
                v0.y = acc[mt][nt][1] + bv1;
                v1.x = acc[mt][nt][2] + bv0;
                v1.y = acc[mt][nt][3] + bv1;
            }
            *(float2*)&ys[(size_t)row * 256 + col] = v0;
            *(float2*)&ys[(size_t)(row + 8) * 256 + col] = v1;
        }
    }
}

// ---------------------------------------------------------------------------
// GEMM2: h = leaky_relu( pooled @ Wn^T + s )   where s = ys[:,128:256]
// CTA 128x128, 256 threads (8 warps, 2x4).
__global__ void __launch_bounds__(256) gemm2_kernel(
    const float* __restrict__ pooled, const float* __restrict__ Wn,
    const float* __restrict__ ys, float* __restrict__ h)
{
    extern __shared__ uint32_t smem[];
    uint32_t* As = smem;                 // [128][132]
    uint32_t* Bs = smem + 128 * 132;     // [128][132]

    const int tid = threadIdx.x;
    const int lane = tid & 31;
    const int wid = tid >> 5;
    const int wn = wid & 3;
    const int wm = wid >> 2;
    const int g = lane >> 2;
    const int t4 = lane & 3;
    const int m0 = blockIdx.x * 128;

    float acc[4][4][4];
#pragma unroll
    for (int mt = 0; mt < 4; mt++)
#pragma unroll
        for (int nt = 0; nt < 4; nt++)
#pragma unroll
            for (int r = 0; r < 4; r++) acc[mt][nt][r] = 0.f;

    stage_async<128, 256>(As, pooled + (size_t)m0 * 128, tid);
    stage_async<128, 256>(Bs, Wn, tid);
    CP_COMMIT();
    CP_WAIT0();
    __syncthreads();

    mma_mainloop(As, Bs, acc, wm, wn, g, t4);

#pragma unroll
    for (int mt = 0; mt < 4; mt++) {
        int row = m0 + wm * 64 + mt * 16 + g;
#pragma unroll
        for (int nt = 0; nt < 4; nt++) {
            int col = wn * 32 + nt * 8 + 2 * t4;      // 0..127
            float2 s0 = *(const float2*)&ys[(size_t)row * 256 + 128 + col];
            float2 s1 = *(const float2*)&ys[(size_t)(row + 8) * 256 + 128 + col];
            float2 v0, v1;
            v0.x = act_fn<2>(acc[mt][nt][0] + s0.x);
            v0.y = act_fn<2>(acc[mt][nt][1] + s0.y);
            v1.x = act_fn<2>(acc[mt][nt][2] + s1.x);
            v1.y = act_fn<2>(acc[mt][nt][3] + s1.y);
            *(float2*)&h[(size_t)row * 128 + col] = v0;
            *(float2*)&h[(size_t)(row + 8) * 128 + col] = v1;
        }
    }
}

// ---------------------------------------------------------------------------
// GEMM3: h2 = leaky_relu(h @ W1^T + b1)  — CTA 128x256, 512 threads.
__global__ void __launch_bounds__(512) gemm3_kernel(
    const float* __restrict__ h, const float* __restrict__ W1,
    const float* __restrict__ b1, float* __restrict__ h2)
{
    extern __shared__ uint32_t smem[];
    uint32_t* As = smem;                 // [128][132]
    uint32_t* Bs = smem + 128 * 132;     // [256][132]

    const int tid = threadIdx.x;
    const int lane = tid & 31;
    const int wid = tid >> 5;
    const int wn = wid & 7;
    const int wm = wid >> 3;
    const int g = lane >> 2;
    const int t4 = lane & 3;
    const int m0 = blockIdx.x * 128;

    float acc[4][4][4];
#pragma unroll
    for (int mt = 0; mt < 4; mt++)
#pragma unroll
        for (int nt = 0; nt < 4; nt++)
#pragma unroll
            for (int r = 0; r < 4; r++) acc[mt][nt][r] = 0.f;

    stage_async<128, 512>(As, h + (size_t)m0 * 128, tid);
    stage_async<256, 512>(Bs, W1, tid);
    CP_COMMIT();
    CP_WAIT0();
    __syncthreads();

    mma_mainloop(As, Bs, acc, wm, wn, g, t4);

#pragma unroll
    for (int mt = 0; mt < 4; mt++) {
        int row = m0 + wm * 64 + mt * 16 + g;
#pragma unroll
        for (int nt = 0; nt < 4; nt++) {
            int col = wn * 32 + nt * 8 + 2 * t4;      // 0..255
            float bv0 = __ldg(&b1[col]);
            float bv1 = __ldg(&b1[col + 1]);
            float2 v0, v1;
            v0.x = act_fn<2>(acc[mt][nt][0] + bv0);
            v0.y = act_fn<2>(acc[mt][nt][1] + bv1);
            v1.x = act_fn<2>(acc[mt][nt][2] + bv0);
            v1.y = act_fn<2>(acc[mt][nt][3] + bv1);
            *(float2*)&h2[(size_t)row * 256 + col] = v0;
            *(float2*)&h2[(size_t)(row + 8) * 256 + col] = v1;
        }
    }
}

// ---------------------------------------------------------------------------
// Edge-phase kernels
__global__ void hist_kernel(const int* __restrict__ dst, int* __restrict__ deg) {
    int e = blockIdx.x * blockDim.x + threadIdx.x;
    if (e < N_EDGES) atomicAdd(&deg[dst[e]], 1);
}

// Warp-aggregated segment placement: order-free CSR offsets.
__global__ void __launch_bounds__(256) offsets_kernel(
    int* __restrict__ deg, int* __restrict__ off, int* __restrict__ cursor)
{
    int n = blockIdx.x * blockDim.x + threadIdx.x;
    int lane = threadIdx.x & 31;
    int d = deg[n];
    int incl = d;
#pragma unroll
    for (int o = 1; o < 32; o <<= 1) {
        int v = __shfl_up_sync(0xFFFFFFFFu, incl, o);
        if (lane >= o) incl += v;
    }
    int tot = __shfl_sync(0xFFFFFFFFu, incl, 31);
    int base = 0;
    if (lane == 31) base = atomicAdd(&deg[N_NODES], tot);  // global cursor slot
    base = __shfl_sync(0xFFFFFFFFu, base, 31);
    int start = base + incl - d;
    off[n] = start;
    cursor[n] = start;
}

__global__ void fill_kernel(const int* __restrict__ src, const int* __restrict__ dst,
                            int* __restrict__ cursor, int* __restrict__ csr) {
    int e = blockIdx.x * blockDim.x + threadIdx.x;
    if (e < N_EDGES) {
        int p = atomicAdd(&cursor[dst[e]], 1);
        csr[p] = src[e];
    }
}

__device__ __forceinline__ void max4(float4& m, float4 v) {
    m.x = fmaxf(m.x, v.x);
    m.y = fmaxf(m.y, v.y);
    m.z = fmaxf(m.z, v.z);
    m.w = fmaxf(m.w, v.w);
}

// One warp per node, 4 edges in flight. y rows live in ys[:,0:128] (stride 256).
__global__ void __launch_bounds__(256) pool_max_kernel(
    const int* __restrict__ off, const int* __restrict__ deg,
    const int* __restrict__ csr, const float* __restrict__ ys,
    float* __restrict__ pooled)
{
    int warp = (blockIdx.x * blockDim.x + threadIdx.x) >> 5;
    if (warp >= N_NODES) return;
    int lane = threadIdx.x & 31;
    int beg = off[warp];
    int end = beg + deg[warp];
    float4 m = make_float4(0.f, 0.f, 0.f, 0.f);
    int e = beg;
    for (; e + 4 <= end; e += 4) {
        int s0 = __ldg(&csr[e + 0]);
        int s1 = __ldg(&csr[e + 1]);
        int s2 = __ldg(&csr[e + 2]);
        int s3 = __ldg(&csr[e + 3]);
        float4 v0 = *(const float4*)&ys[(size_t)s0 * 256 + lane * 4];
        float4 v1 = *(const float4*)&ys[(size_t)s1 * 256 + lane * 4];
        float4 v2 = *(const float4*)&ys[(size_t)s2 * 256 + lane * 4];
        float4 v3 = *(const float4*)&ys[(size_t)s3 * 256 + lane * 4];
        max4(m, v0);
        max4(m, v1);
        max4(m, v2);
        max4(m, v3);
    }
    for (; e < end; e++) {
        int s = __ldg(&csr[e]);
        float4 v = *(const float4*)&ys[(size_t)s * 256 + lane * 4];
        max4(m, v);
    }
    *(float4*)&pooled[(size_t)warp * H1 + lane * 4] = m;
}

// ---------------------------------------------------------------------------
__global__ void __launch_bounds__(256) head_kernel(
    const float* __restrict__ h2, const float* __restrict__ W2,
    const float* __restrict__ b2, float* __restrict__ out)
{
    __shared__ float Wt[H2 * N_CLASSES];
    int tid = threadIdx.x;
    for (int i = tid; i < N_CLASSES * H2; i += 256) {
        int c = i / H2;
        int k = i % H2;
        Wt[k * N_CLASSES + c] = W2[i];
    }
    __syncthreads();

    int node = blockIdx.x * 16 + (tid >> 4);
    int c = tid & 15;
    const float* hrow = &h2[(size_t)node * H2];
    float s = 0.f;
#pragma unroll 8
    for (int k = 0; k < H2; k += 4) {
        float4 hv = *(const float4*)&hrow[k];
        s += hv.x * Wt[(k + 0) * N_CLASSES + c];
        s += hv.y * Wt[(k + 1) * N_CLASSES + c];
        s += hv.z * Wt[(k + 2) * N_CLASSES + c];
        s += hv.w * Wt[(k + 3) * N_CLASSES + c];
    }
    s += b2[c];
    out[(size_t)node * N_CLASSES + c] = 1.f / (1.f + expf(-s));
}

// ---------------------------------------------------------------------------
extern "C" void kernel_launch(void* const* d_in, const int* in_sizes, int n_in,
                              void* d_out, int out_size)
{
    const float* x  = (const float*)d_in[0];
    const float* Wp = (const float*)d_in[1];
    const float* bp = (const float*)d_in[2];
    const float* Ws = (const float*)d_in[3];
    const float* Wn = (const float*)d_in[4];
    const float* bn = (const float*)d_in[5];
    const float* W1 = (const float*)d_in[6];
    const float* b1 = (const float*)d_in[7];
    const float* W2 = (const float*)d_in[8];
    const float* b2 = (const float*)d_in[9];
    const int* src  = (const int*)d_in[10];
    const int* dst  = (const int*)d_in[11];
    float* out = (float*)d_out;

    float *ys_p, *pooled_p, *h_p, *h2_p;
    int *deg_p, *off_p, *cur_p, *csr_p;
    cudaGetSymbolAddress((void**)&ys_p, g_ys);
    cudaGetSymbolAddress((void**)&pooled_p, g_pooled);
    cudaGetSymbolAddress((void**)&h_p, g_h);
    cudaGetSymbolAddress((void**)&h2_p, g_h2);
    cudaGetSymbolAddress((void**)&deg_p, g_deg);
    cudaGetSymbolAddress((void**)&off_p, g_off);
    cudaGetSymbolAddress((void**)&cur_p, g_cursor);
    cudaGetSymbolAddress((void**)&csr_p, g_csr_src);

    const int SMEM_128 = (128 + 128) * 132 * 4;  // 135168 B
    const int SMEM_256 = (128 + 256) * 132 * 4;  // 202752 B
    cudaFuncSetAttribute(gemm1_fused_kernel,
                         cudaFuncAttributeMaxDynamicSharedMemorySize, SMEM_256);
    cudaFuncSetAttribute(gemm2_kernel,
                         cudaFuncAttributeMaxDynamicSharedMemorySize, SMEM_128);
    cudaFuncSetAttribute(gemm3_kernel,
                         cudaFuncAttributeMaxDynamicSharedMemorySize, SMEM_256);

    // CSR build (order-free offsets; deg[N_NODES] doubles as global cursor)
    cudaMemsetAsync(deg_p, 0, (N_NODES + 1) * sizeof(int));
    hist_kernel<<<N_EDGES / 256, 256>>>(dst, deg_p);
    offsets_kernel<<<N_NODES / 256, 256>>>(deg_p, off_p, cur_p);
    fill_kernel<<<N_EDGES / 256, 256>>>(src, dst, cur_p, csr_p);

    // ys = [ relu(x@Wp^T+bp) | x@Ws^T+bn ]
    gemm1_fused_kernel<<<N_NODES / 128, 512, SMEM_256>>>(x, Wp, Ws, bp, bn, ys_p);

    // pooled[n] = max over incoming edges of y[src]
    pool_max_kernel<<<N_NODES * 32 / 256, 256>>>(off_p, deg_p, csr_p, ys_p, pooled_p);

    // h = leaky_relu(pooled @ Wn^T + s)
    gemm2_kernel<<<N_NODES / 128, 256, SMEM_128>>>(pooled_p, Wn, ys_p, h_p);

    // h2 = leaky_relu(h @ W1^T + b1)
    gemm3_kernel<<<N_NODES / 128, 512, SMEM_256>>>(h_p, W1, b1, h2_p);

    // out = sigmoid(h2 @ W2^T + b2)
    head_kernel<<<N_NODES / 16, 256>>>(h2_p, W2, b2, out);
}